// round 5
// baseline (speedup 1.0000x reference)
#include <cuda_runtime.h>

// CCM_77043123355820: per-frequency 3x3 complex tap filter + cache shift.
// F_BINS = 257.
// Inputs (metadata order): m (27*257 f32), x (257*2 f32), cache (257*2*2 f32)
// Output: x_enh (257*2 f32) followed by new_cache (257*2*2 f32) = 1542 f32.
// NOTE: new_cache region starts at float offset 514 (byte 2056) -> only 8B
// aligned, so stores there must be float2, not float4.

#define F_BINS 257

__global__ void __launch_bounds__(32) ccm_kernel(
    const float* __restrict__ m,
    const float* __restrict__ x,
    const float* __restrict__ cache,
    float* __restrict__ out)
{
    int f = blockIdx.x * blockDim.x + threadIdx.x;
    if (f >= F_BINS) return;

    // ---- front-batch all 27 m loads (independent, max MLP) ----
    float mv[27];
#pragma unroll
    for (int c = 0; c < 27; c++)
        mv[c] = __ldg(&m[c * F_BINS + f]);

    const float4* __restrict__ c4 = (const float4*)cache;  // (c0r,c0i,c1r,c1i) per f
    const float2* __restrict__ x2 = (const float2*)x;      // (xr,xi) per f

    // ---- gather X window at f-1, f, f+1 (vector loads, branchless zero mask) ----
    int gm = f - 1;
    int gp = f + 1;
    float wl = (gm >= 0)     ? 1.0f : 0.0f;
    float wr = (gp < F_BINS) ? 1.0f : 0.0f;
    int gml = (gm >= 0)     ? gm : 0;
    int gpc = (gp < F_BINS) ? gp : F_BINS - 1;

    float4 cl = c4[gml];
    float4 cc = c4[f];
    float4 cr = c4[gpc];
    float2 xl  = x2[gml];
    float2 xc  = x2[f];
    float2 xr2 = x2[gpc];

    // Xr[i][j], Xi[i][j]: i=time (0,1 from cache; 2 from x), j=freq offset
    float Xr[3][3], Xi[3][3];
    Xr[0][0] = cl.x * wl;  Xi[0][0] = cl.y * wl;
    Xr[1][0] = cl.z * wl;  Xi[1][0] = cl.w * wl;
    Xr[2][0] = xl.x * wl;  Xi[2][0] = xl.y * wl;
    Xr[0][1] = cc.x;       Xi[0][1] = cc.y;
    Xr[1][1] = cc.z;       Xi[1][1] = cc.w;
    Xr[2][1] = xc.x;       Xi[2][1] = xc.y;
    Xr[0][2] = cr.x * wr;  Xi[0][2] = cr.y * wr;
    Xr[1][2] = cr.z * wr;  Xi[1][2] = cr.w * wr;
    Xr[2][2] = xr2.x * wr; Xi[2][2] = xr2.y * wr;

    // ---- new_cache: shift time window (two 8B-aligned float2 stores) ----
    float2* nc2 = (float2*)(out + 2 * F_BINS);
    nc2[f * 2 + 0] = make_float2(cc.z, cc.w);
    nc2[f * 2 + 1] = xc;

    // ---- accumulate complex taps: 3 independent accumulator pairs ----
    const float S3H = 0.86602540378443864676f;  // sqrt(3)/2
    float ar[3] = {0.f, 0.f, 0.f};
    float ai[3] = {0.f, 0.f, 0.f};
#pragma unroll
    for (int i = 0; i < 3; i++) {
#pragma unroll
        for (int j = 0; j < 3; j++) {
            int k = i * 3 + j;
            float m0 = mv[k];
            float m1 = mv[9 + k];
            float m2 = mv[18 + k];
            float Mr = fmaf(-0.5f, m1 + m2, m0);
            float Mi = S3H * (m1 - m2);
            float vr = Xr[i][j], vi = Xi[i][j];
            ar[i] = fmaf(Mr, vr, ar[i]);
            ar[i] = fmaf(-Mi, vi, ar[i]);
            ai[i] = fmaf(Mr, vi, ai[i]);
            ai[i] = fmaf(Mi, vr, ai[i]);
        }
    }
    float acc_r = (ar[0] + ar[1]) + ar[2];
    float acc_i = (ai[0] + ai[1]) + ai[2];

    ((float2*)out)[f] = make_float2(acc_r, acc_i);
}

extern "C" void kernel_launch(void* const* d_in, const int* in_sizes, int n_in,
                              void* d_out, int out_size) {
    const float* m     = (const float*)d_in[0];
    const float* x     = (const float*)d_in[1];
    const float* cache = (const float*)d_in[2];
    float* out = (float*)d_out;

    ccm_kernel<<<(F_BINS + 31) / 32, 32>>>(m, x, cache, out);
}

// round 6
// speedup vs baseline: 1.2135x; 1.2135x over previous
#include <cuda_runtime.h>

// CCM_77043123355820: per-frequency 3x3 complex tap filter + cache shift.
// F_BINS = 257.
// Inputs (metadata order): m (27*257 f32), x (257*2 f32), cache (257*2*2 f32)
// Output: x_enh (257*2 f32) followed by new_cache (257*2*2 f32) = 1542 f32.
// NOTE: new_cache region starts at float offset 514 (byte 2056) -> only 8B
// aligned, so stores there must be float2, not float4.
//
// R6 = exact revert to R4 (best measured: 4.58us). R5's load-batching +
// accumulator split showed identical ncu kernel time but worse wallclock;
// this revert is the control to separate harness timing noise from real
// kernel-body deltas.

#define F_BINS 257

__global__ void __launch_bounds__(32) ccm_kernel(
    const float* __restrict__ m,
    const float* __restrict__ x,
    const float* __restrict__ cache,
    float* __restrict__ out)
{
    int f = blockIdx.x * blockDim.x + threadIdx.x;
    if (f >= F_BINS) return;

    const float4* __restrict__ c4 = (const float4*)cache;  // (c0r,c0i,c1r,c1i) per f
    const float2* __restrict__ x2 = (const float2*)x;      // (xr,xi) per f

    // ---- gather X window at f-1, f, f+1 (vector loads, branchless zero mask) ----
    int gm = f - 1;
    int gp = f + 1;
    float wl = (gm >= 0)     ? 1.0f : 0.0f;
    float wr = (gp < F_BINS) ? 1.0f : 0.0f;
    int gml = (gm >= 0)     ? gm : 0;
    int gpc = (gp < F_BINS) ? gp : F_BINS - 1;

    float4 cl = c4[gml];
    float4 cc = c4[f];
    float4 cr = c4[gpc];
    float2 xl  = x2[gml];
    float2 xc  = x2[f];
    float2 xr2 = x2[gpc];

    // Xr[i][j], Xi[i][j]: i=time (0,1 from cache; 2 from x), j=freq offset
    float Xr[3][3], Xi[3][3];
    Xr[0][0] = cl.x * wl;  Xi[0][0] = cl.y * wl;
    Xr[1][0] = cl.z * wl;  Xi[1][0] = cl.w * wl;
    Xr[2][0] = xl.x * wl;  Xi[2][0] = xl.y * wl;
    Xr[0][1] = cc.x;       Xi[0][1] = cc.y;
    Xr[1][1] = cc.z;       Xi[1][1] = cc.w;
    Xr[2][1] = xc.x;       Xi[2][1] = xc.y;
    Xr[0][2] = cr.x * wr;  Xi[0][2] = cr.y * wr;
    Xr[1][2] = cr.z * wr;  Xi[1][2] = cr.w * wr;
    Xr[2][2] = xr2.x * wr; Xi[2][2] = xr2.y * wr;

    // ---- new_cache: shift time window (two 8B-aligned float2 stores) ----
    float2* nc2 = (float2*)(out + 2 * F_BINS);
    nc2[f * 2 + 0] = make_float2(cc.z, cc.w);
    nc2[f * 2 + 1] = xc;

    // ---- accumulate complex taps ----
    const float S3H = 0.86602540378443864676f;  // sqrt(3)/2
    float acc_r = 0.0f, acc_i = 0.0f;
#pragma unroll
    for (int i = 0; i < 3; i++) {
#pragma unroll
        for (int j = 0; j < 3; j++) {
            int k = i * 3 + j;
            float m0 = __ldg(&m[(0 * 9 + k) * F_BINS + f]);
            float m1 = __ldg(&m[(1 * 9 + k) * F_BINS + f]);
            float m2 = __ldg(&m[(2 * 9 + k) * F_BINS + f]);
            float Mr = fmaf(-0.5f, m1 + m2, m0);
            float Mi = S3H * (m1 - m2);
            float vr = Xr[i][j], vi = Xi[i][j];
            acc_r = fmaf(Mr, vr, acc_r);
            acc_r = fmaf(-Mi, vi, acc_r);
            acc_i = fmaf(Mr, vi, acc_i);
            acc_i = fmaf(Mi, vr, acc_i);
        }
    }

    ((float2*)out)[f] = make_float2(acc_r, acc_i);
}

extern "C" void kernel_launch(void* const* d_in, const int* in_sizes, int n_in,
                              void* d_out, int out_size) {
    const float* m     = (const float*)d_in[0];
    const float* x     = (const float*)d_in[1];
    const float* cache = (const float*)d_in[2];
    float* out = (float*)d_out;

    ccm_kernel<<<(F_BINS + 31) / 32, 32>>>(m, x, cache, out);
}

// round 7
// speedup vs baseline: 1.5105x; 1.2448x over previous
#include <cuda_runtime.h>

// CCM_77043123355820: per-frequency 3x3 complex tap filter + cache shift.
// F_BINS = 257.
// Inputs (metadata order): m (27*257 f32), x (257*2 f32), cache (257*2*2 f32)
// Output: x_enh (257*2 f32) followed by new_cache (257*2*2 f32) = 1542 f32.
// NOTE: new_cache region starts at float offset 514 (byte 2056) -> only 8B
// aligned, so stores there must be float2, not float4.
//
// R7 = R4 body (best measured 4.58us), launch shape 3x96 instead of 9x32
// (same 9 warps, fewer CTAs to dispatch). Kernel is at the single-launch
// latency floor: wallclock noise (R4=4.58, R6=5.70 on identical source)
// exceeds any remaining body-level delta.

#define F_BINS 257

__global__ void __launch_bounds__(96) ccm_kernel(
    const float* __restrict__ m,
    const float* __restrict__ x,
    const float* __restrict__ cache,
    float* __restrict__ out)
{
    int f = blockIdx.x * blockDim.x + threadIdx.x;
    if (f >= F_BINS) return;

    const float4* __restrict__ c4 = (const float4*)cache;  // (c0r,c0i,c1r,c1i) per f
    const float2* __restrict__ x2 = (const float2*)x;      // (xr,xi) per f

    // ---- gather X window at f-1, f, f+1 (vector loads, branchless zero mask) ----
    int gm = f - 1;
    int gp = f + 1;
    float wl = (gm >= 0)     ? 1.0f : 0.0f;
    float wr = (gp < F_BINS) ? 1.0f : 0.0f;
    int gml = (gm >= 0)     ? gm : 0;
    int gpc = (gp < F_BINS) ? gp : F_BINS - 1;

    float4 cl = c4[gml];
    float4 cc = c4[f];
    float4 cr = c4[gpc];
    float2 xl  = x2[gml];
    float2 xc  = x2[f];
    float2 xr2 = x2[gpc];

    // Xr[i][j], Xi[i][j]: i=time (0,1 from cache; 2 from x), j=freq offset
    float Xr[3][3], Xi[3][3];
    Xr[0][0] = cl.x * wl;  Xi[0][0] = cl.y * wl;
    Xr[1][0] = cl.z * wl;  Xi[1][0] = cl.w * wl;
    Xr[2][0] = xl.x * wl;  Xi[2][0] = xl.y * wl;
    Xr[0][1] = cc.x;       Xi[0][1] = cc.y;
    Xr[1][1] = cc.z;       Xi[1][1] = cc.w;
    Xr[2][1] = xc.x;       Xi[2][1] = xc.y;
    Xr[0][2] = cr.x * wr;  Xi[0][2] = cr.y * wr;
    Xr[1][2] = cr.z * wr;  Xi[1][2] = cr.w * wr;
    Xr[2][2] = xr2.x * wr; Xi[2][2] = xr2.y * wr;

    // ---- new_cache: shift time window (two 8B-aligned float2 stores) ----
    float2* nc2 = (float2*)(out + 2 * F_BINS);
    nc2[f * 2 + 0] = make_float2(cc.z, cc.w);
    nc2[f * 2 + 1] = xc;

    // ---- accumulate complex taps ----
    const float S3H = 0.86602540378443864676f;  // sqrt(3)/2
    float acc_r = 0.0f, acc_i = 0.0f;
#pragma unroll
    for (int i = 0; i < 3; i++) {
#pragma unroll
        for (int j = 0; j < 3; j++) {
            int k = i * 3 + j;
            float m0 = __ldg(&m[(0 * 9 + k) * F_BINS + f]);
            float m1 = __ldg(&m[(1 * 9 + k) * F_BINS + f]);
            float m2 = __ldg(&m[(2 * 9 + k) * F_BINS + f]);
            float Mr = fmaf(-0.5f, m1 + m2, m0);
            float Mi = S3H * (m1 - m2);
            float vr = Xr[i][j], vi = Xi[i][j];
            acc_r = fmaf(Mr, vr, acc_r);
            acc_r = fmaf(-Mi, vi, acc_r);
            acc_i = fmaf(Mr, vi, acc_i);
            acc_i = fmaf(Mi, vr, acc_i);
        }
    }

    ((float2*)out)[f] = make_float2(acc_r, acc_i);
}

extern "C" void kernel_launch(void* const* d_in, const int* in_sizes, int n_in,
                              void* d_out, int out_size) {
    const float* m     = (const float*)d_in[0];
    const float* x     = (const float*)d_in[1];
    const float* cache = (const float*)d_in[2];
    float* out = (float*)d_out;

    ccm_kernel<<<(F_BINS + 95) / 96, 96>>>(m, x, cache, out);
}